// round 1
// baseline (speedup 1.0000x reference)
#include <cuda_runtime.h>

// ---------------- problem constants (fixed shapes) ----------------
#define D_IN    1024
#define M_HID   4096
#define R_LORA  16
#define BATCH   16384
#define LSCALE  2.0f     // ALPHA / R = 32/16

// ---------------- tiling ----------------
#define BM 128
#define BN 128
#define BK 16
#define SMS 132              // padded smem row stride (floats)
#define NTHREADS 256
#define MTILES (M_HID / BN)  // 32
#define BTILES (BATCH / BM)  // 128

typedef unsigned long long ull;

// scratch (static device globals — no allocation)
__device__ float g_t[BATCH * R_LORA];          // 1 MB : t = x @ A^T
__device__ float g_partial[MTILES * BATCH];    // 2 MB : per-m-tile partial dots

// ---------------- packed f32x2 helpers ----------------
__device__ __forceinline__ ull ffma2(ull a, ull b, ull c) {
    ull d;
    asm("fma.rn.f32x2 %0, %1, %2, %3;" : "=l"(d) : "l"(a), "l"(b), "l"(c));
    return d;
}
__device__ __forceinline__ ull pack_dup(float v) {
    ull d;
    asm("mov.b64 %0, {%1, %1};" : "=l"(d) : "r"(__float_as_uint(v)));
    return d;
}
__device__ __forceinline__ float2 unpack2(ull v) {
    unsigned lo, hi;
    asm("mov.b64 {%0, %1}, %2;" : "=r"(lo), "=r"(hi) : "l"(v));
    float2 r; r.x = __uint_as_float(lo); r.y = __uint_as_float(hi);
    return r;
}

// ==================================================================
// Kernel 1: t[b][r] = sum_d x[b][d] * A[r][d]
// 512 blocks x 256 threads; 32 batch rows per block; A staged in smem.
// ==================================================================
__global__ __launch_bounds__(256) void compute_t_kernel(
    const float* __restrict__ x, const float* __restrict__ A)
{
    __shared__ float As[R_LORA * 256];   // 16 KB chunk of A
    const int tid = threadIdx.x;
    const int rowLocal = tid >> 3;   // 0..31
    const int sub      = tid & 7;    // 0..7
    const int b = blockIdx.x * 32 + rowLocal;

    float acc[R_LORA];
#pragma unroll
    for (int r = 0; r < R_LORA; ++r) acc[r] = 0.f;

    for (int d0 = 0; d0 < D_IN; d0 += 256) {
        __syncthreads();
#pragma unroll
        for (int q = 0; q < 4; ++q) {
            int f   = tid + q * 256;   // float4 index 0..1023
            int r   = f >> 6;
            int dd4 = f & 63;
            ((float4*)As)[r * 64 + dd4] =
                *(const float4*)(A + (size_t)r * D_IN + d0 + dd4 * 4);
        }
        __syncthreads();
#pragma unroll 8
        for (int q = 0; q < 32; ++q) {
            int dd = sub + 8 * q;    // stride-8 so same-sub lanes broadcast
            float xv = x[(size_t)b * D_IN + d0 + dd];
#pragma unroll
            for (int r = 0; r < R_LORA; ++r)
                acc[r] = fmaf(xv, As[r * 256 + dd], acc[r]);
        }
    }
    // reduce over 8 subs (sub = low 3 bits of lane)
#pragma unroll
    for (int r = 0; r < R_LORA; ++r) {
        acc[r] += __shfl_down_sync(0xffffffffu, acc[r], 4);
        acc[r] += __shfl_down_sync(0xffffffffu, acc[r], 2);
        acc[r] += __shfl_down_sync(0xffffffffu, acc[r], 1);
    }
    if (sub == 0) {
#pragma unroll
        for (int r = 0; r < R_LORA; ++r)
            g_t[(size_t)b * R_LORA + r] = acc[r];
    }
}

// ==================================================================
// Kernel 2: fused GEMM + LoRA + bias + relu + dot(W2) tile-reduction
// Grid: (MTILES, BTILES), 256 threads, 128x128 tile, 8x8/thread.
// ==================================================================
__device__ __forceinline__ void tile_accum(
    const float* __restrict__ xs, const float* __restrict__ ws,
    int i0, int j0, ull acc[8][4])
{
#pragma unroll
    for (int k = 0; k < BK; ++k) {
        float4 a0 = *(const float4*)&xs[k * SMS + i0];
        float4 a1 = *(const float4*)&xs[k * SMS + i0 + 4];
        const ull* bp = (const ull*)&ws[k * SMS + j0];
        ull b0 = bp[0], b1 = bp[1], b2 = bp[2], b3 = bp[3];
        float av[8] = {a0.x, a0.y, a0.z, a0.w, a1.x, a1.y, a1.z, a1.w};
#pragma unroll
        for (int ii = 0; ii < 8; ++ii) {
            ull ad = pack_dup(av[ii]);
            acc[ii][0] = ffma2(ad, b0, acc[ii][0]);
            acc[ii][1] = ffma2(ad, b1, acc[ii][1]);
            acc[ii][2] = ffma2(ad, b2, acc[ii][2]);
            acc[ii][3] = ffma2(ad, b3, acc[ii][3]);
        }
    }
}

__global__ __launch_bounds__(NTHREADS, 2) void fused_main_kernel(
    const float* __restrict__ x,   const float* __restrict__ W0,
    const float* __restrict__ b0v, const float* __restrict__ Bm,
    const float* __restrict__ W2)
{
    __shared__ __align__(16) float sm[2 * BK * SMS];   // 16.9 KB
    float* xs = sm;
    float* ws = sm + BK * SMS;

    const int tid = threadIdx.x;
    const int tx  = tid & 15;          // n-group
    const int ty  = tid >> 4;          // m-group
    const int i0  = ty * 8;
    const int j0  = tx * 8;
    const int m0  = blockIdx.x * BN;
    const int bb0 = blockIdx.y * BM;

    ull acc[8][4];
#pragma unroll
    for (int ii = 0; ii < 8; ++ii)
#pragma unroll
        for (int p = 0; p < 4; ++p) acc[ii][p] = 0ull;

    // ---- LoRA pre-pass: one BK=16 tile using t (scaled) and B ----
    {
        int i  = tid & 127;
        int rh = tid >> 7;   // 0 or 1
        int rb = rh * 8;
        const float4* tp  = (const float4*)(g_t + (size_t)(bb0 + i) * R_LORA + rb);
        float4 u0 = tp[0], u1 = tp[1];
        xs[(rb + 0) * SMS + i] = u0.x;  xs[(rb + 1) * SMS + i] = u0.y;
        xs[(rb + 2) * SMS + i] = u0.z;  xs[(rb + 3) * SMS + i] = u0.w;
        xs[(rb + 4) * SMS + i] = u1.x;  xs[(rb + 5) * SMS + i] = u1.y;
        xs[(rb + 6) * SMS + i] = u1.z;  xs[(rb + 7) * SMS + i] = u1.w;
        const float4* bp4 = (const float4*)(Bm + (size_t)(m0 + i) * R_LORA + rb);
        float4 v0 = bp4[0], v1 = bp4[1];
        ws[(rb + 0) * SMS + i] = LSCALE * v0.x;  ws[(rb + 1) * SMS + i] = LSCALE * v0.y;
        ws[(rb + 2) * SMS + i] = LSCALE * v0.z;  ws[(rb + 3) * SMS + i] = LSCALE * v0.w;
        ws[(rb + 4) * SMS + i] = LSCALE * v1.x;  ws[(rb + 5) * SMS + i] = LSCALE * v1.y;
        ws[(rb + 6) * SMS + i] = LSCALE * v1.z;  ws[(rb + 7) * SMS + i] = LSCALE * v1.w;
    }
    __syncthreads();
    tile_accum(xs, ws, i0, j0, acc);

    // ---- main K loop over x @ W0^T ----
    const float* xsrc = x  + (size_t)bb0 * D_IN;
    const float* wsrc = W0 + (size_t)m0  * D_IN;
    for (int kt = 0; kt < D_IN / BK; ++kt) {
        __syncthreads();   // protect previous tile reads / lora pass
#pragma unroll
        for (int rep = 0; rep < 2; ++rep) {
            int f  = tid + rep * 256;    // 0..511 float4 slots
            int i  = f >> 2;
            int kp = f & 3;
            float4 v = *(const float4*)(xsrc + (size_t)i * D_IN + kt * BK + kp * 4);
            xs[(kp * 4 + 0) * SMS + i] = v.x;
            xs[(kp * 4 + 1) * SMS + i] = v.y;
            xs[(kp * 4 + 2) * SMS + i] = v.z;
            xs[(kp * 4 + 3) * SMS + i] = v.w;
            float4 w = *(const float4*)(wsrc + (size_t)i * D_IN + kt * BK + kp * 4);
            ws[(kp * 4 + 0) * SMS + i] = w.x;
            ws[(kp * 4 + 1) * SMS + i] = w.y;
            ws[(kp * 4 + 2) * SMS + i] = w.z;
            ws[(kp * 4 + 3) * SMS + i] = w.w;
        }
        __syncthreads();
        tile_accum(xs, ws, i0, j0, acc);
    }

    // ---- epilogue: bias + relu + dot with W2, reduce over the 128 cols ----
    float biasr[8], w2r[8];
#pragma unroll
    for (int jj = 0; jj < 8; ++jj) {
        biasr[jj] = b0v[m0 + j0 + jj];
        w2r[jj]   = W2[m0 + j0 + jj];
    }
    float rowsum[8];
#pragma unroll
    for (int ii = 0; ii < 8; ++ii) {
        float s = 0.f;
#pragma unroll
        for (int p = 0; p < 4; ++p) {
            float2 hv = unpack2(acc[ii][p]);
            float h0 = hv.x + biasr[p * 2];
            float h1 = hv.y + biasr[p * 2 + 1];
            s = fmaf(fmaxf(h0, 0.f), w2r[p * 2], s);
            s = fmaf(fmaxf(h1, 0.f), w2r[p * 2 + 1], s);
        }
        rowsum[ii] = s;
    }

    __syncthreads();   // smem reuse for reduction
    float* red = sm;   // [128][17] = 2176 floats <= 4224 available
#pragma unroll
    for (int ii = 0; ii < 8; ++ii)
        red[(i0 + ii) * 17 + tx] = rowsum[ii];
    __syncthreads();

    if (tid < BM) {
        float s = 0.f;
#pragma unroll
        for (int q = 0; q < 16; ++q) s += red[tid * 17 + q];
        g_partial[(size_t)blockIdx.x * BATCH + bb0 + tid] = s;
    }
}

// ==================================================================
// Kernel 3: out[b] = b2 + sum_mt partial[mt][b]
// ==================================================================
__global__ __launch_bounds__(256) void finalize_kernel(
    const float* __restrict__ b2, float* __restrict__ out)
{
    int b = blockIdx.x * 256 + threadIdx.x;
    float s = b2[0];
#pragma unroll
    for (int mt = 0; mt < MTILES; ++mt)
        s += g_partial[(size_t)mt * BATCH + b];
    out[b] = s;
}

// ==================================================================
extern "C" void kernel_launch(void* const* d_in, const int* in_sizes, int n_in,
                              void* d_out, int out_size)
{
    const float* x   = (const float*)d_in[0];
    const float* W0  = (const float*)d_in[1];
    const float* b0v = (const float*)d_in[2];
    const float* A   = (const float*)d_in[3];
    const float* Bm  = (const float*)d_in[4];
    const float* W2  = (const float*)d_in[5];
    const float* b2  = (const float*)d_in[6];
    float* out = (float*)d_out;

    compute_t_kernel<<<BATCH / 32, 256>>>(x, A);

    dim3 grid(MTILES, BTILES);
    fused_main_kernel<<<grid, NTHREADS>>>(x, W0, b0v, Bm, W2);

    finalize_kernel<<<BATCH / 256, 256>>>(b2, out);
}

// round 3
// speedup vs baseline: 2.6010x; 2.6010x over previous
#include <cuda_runtime.h>
#include <cuda_bf16.h>
#include <cstdint>

// ---------------- problem constants ----------------
#define D_IN    1024
#define M_HID   4096
#define BATCH   16384
#define R_LORA  16
#define LSCALE  2.0f

// ---------------- GEMM tiling ----------------
#define BM      256                 // batch rows per CTA
#define BN      128                 // hidden cols per CTA
#define BK      32                  // bf16 K per stage
#define KITERS  (D_IN / BK)         // 32
#define NT      (M_HID / BN)        // 32
#define MT      (BATCH / BM)        // 64
#define NTHREADS 256

// smem layout (bytes). rows have stride 80B (32 bf16 + 8 pad) -> conflict-free ldmatrix
#define ROWB    80
#define XB      (BM * ROWB)          // 20480 per X tensor per stage
#define WB      (BN * ROWB)          // 10240 per W tensor per stage
#define STAGEB  (2*XB + 2*WB)        // 61440
#define BIAS_OFF (2 * STAGEB)        // 122880
#define W2_OFF   (BIAS_OFF + BN*4)
#define RED_OFF  (W2_OFF + BN*4)
#define SMEM_TOTAL (RED_OFF + BM*2*4)   // 125952

// ---------------- scratch (static device globals) ----------------
__device__ __align__(1024) __nv_bfloat16 g_xhi[BATCH * D_IN];   // 32 MB
__device__ __align__(1024) __nv_bfloat16 g_xlo[BATCH * D_IN];   // 32 MB
__device__ __align__(1024) __nv_bfloat16 g_whi[M_HID * D_IN];   //  8 MB
__device__ __align__(1024) __nv_bfloat16 g_wlo[M_HID * D_IN];   //  8 MB
__device__ float g_partial[NT * BATCH];                         //  2 MB

// ---------------- PTX helpers ----------------
__device__ __forceinline__ uint32_t smem_u32(const void* p) {
    uint32_t a;
    asm("{ .reg .u64 t; cvta.to.shared.u64 t, %1; cvt.u32.u64 %0, t; }"
        : "=r"(a) : "l"(p));
    return a;
}

#define CP_ASYNC16(s, g) \
    asm volatile("cp.async.cg.shared.global [%0], [%1], 16;" :: "r"(s), "l"(g) : "memory")
#define CP_COMMIT() asm volatile("cp.async.commit_group;" ::: "memory")
#define CP_WAIT(n)  asm volatile("cp.async.wait_group %0;" :: "n"(n) : "memory")

__device__ __forceinline__ void ldsm4(uint32_t* r, uint32_t addr) {
    asm volatile("ldmatrix.sync.aligned.m8n8.x4.shared.b16 {%0,%1,%2,%3}, [%4];"
                 : "=r"(r[0]), "=r"(r[1]), "=r"(r[2]), "=r"(r[3]) : "r"(addr));
}

__device__ __forceinline__ void mma16816(float* c, const uint32_t* a, const uint32_t* b) {
    asm volatile(
        "mma.sync.aligned.m16n8k16.row.col.f32.bf16.bf16.f32 "
        "{%0,%1,%2,%3}, {%4,%5,%6,%7}, {%8,%9}, {%0,%1,%2,%3};"
        : "+f"(c[0]), "+f"(c[1]), "+f"(c[2]), "+f"(c[3])
        : "r"(a[0]), "r"(a[1]), "r"(a[2]), "r"(a[3]), "r"(b[0]), "r"(b[1]));
}

// ==================================================================
// Kernel A: split x into bf16 hi/lo
// ==================================================================
__device__ __forceinline__ uint32_t pack_bf2(float a, float b) {
    __nv_bfloat162 t = __floats2bfloat162_rn(a, b);
    return *(uint32_t*)&t;
}

__global__ __launch_bounds__(256) void split_x_kernel(const float* __restrict__ x) {
    size_t i = (size_t)blockIdx.x * 256 + threadIdx.x;   // float4 index
    float4 v = ((const float4*)x)[i];
    float hx = __bfloat162float(__float2bfloat16(v.x));
    float hy = __bfloat162float(__float2bfloat16(v.y));
    float hz = __bfloat162float(__float2bfloat16(v.z));
    float hw = __bfloat162float(__float2bfloat16(v.w));
    uint2 hi, lo;
    hi.x = pack_bf2(hx, hy);             hi.y = pack_bf2(hz, hw);
    lo.x = pack_bf2(v.x - hx, v.y - hy); lo.y = pack_bf2(v.z - hz, v.w - hw);
    ((uint2*)g_xhi)[i] = hi;
    ((uint2*)g_xlo)[i] = lo;
}

// ==================================================================
// Kernel B: W_eff = W0 + 2*(B@A), split into bf16 hi/lo
// ==================================================================
__global__ __launch_bounds__(256) void weff_split_kernel(
    const float* __restrict__ W0, const float* __restrict__ A,
    const float* __restrict__ Bm)
{
    int m = blockIdx.x;
    float br[R_LORA];
#pragma unroll
    for (int r = 0; r < R_LORA; ++r) br[r] = Bm[m * R_LORA + r] * LSCALE;

    int d4 = threadIdx.x;
    float4 acc = ((const float4*)(W0 + (size_t)m * D_IN))[d4];
#pragma unroll
    for (int r = 0; r < R_LORA; ++r) {
        float4 a = ((const float4*)(A + (size_t)r * D_IN))[d4];
        acc.x = fmaf(br[r], a.x, acc.x);
        acc.y = fmaf(br[r], a.y, acc.y);
        acc.z = fmaf(br[r], a.z, acc.z);
        acc.w = fmaf(br[r], a.w, acc.w);
    }
    float hx = __bfloat162float(__float2bfloat16(acc.x));
    float hy = __bfloat162float(__float2bfloat16(acc.y));
    float hz = __bfloat162float(__float2bfloat16(acc.z));
    float hw = __bfloat162float(__float2bfloat16(acc.w));
    size_t i = (size_t)m * (D_IN / 4) + d4;
    uint2 hi, lo;
    hi.x = pack_bf2(hx, hy);                 hi.y = pack_bf2(hz, hw);
    lo.x = pack_bf2(acc.x - hx, acc.y - hy); lo.y = pack_bf2(acc.z - hz, acc.w - hw);
    ((uint2*)g_whi)[i] = hi;
    ((uint2*)g_wlo)[i] = lo;
}

// ==================================================================
// Kernel C: mma.sync split-bf16 GEMM + fused relu-dot epilogue
// grid (NT=32, MT=64), 256 threads (8 warps: 4 along M x 2 along N)
// ==================================================================
__device__ __forceinline__ void issue_stage(uint32_t sbase, int k0, int b0, int n0, int tid)
{
#pragma unroll
    for (int i = 0; i < 4; ++i) {          // X: 1024 16B chunks per tensor
        int idx = tid + i * 256;
        int r = idx >> 2, c = idx & 3;
        uint32_t soff = (uint32_t)(r * ROWB + c * 16);
        const __nv_bfloat16* gh = g_xhi + (size_t)(b0 + r) * D_IN + k0 + c * 8;
        const __nv_bfloat16* gl = g_xlo + (size_t)(b0 + r) * D_IN + k0 + c * 8;
        CP_ASYNC16(sbase + soff, gh);
        CP_ASYNC16(sbase + XB + soff, gl);
    }
#pragma unroll
    for (int i = 0; i < 2; ++i) {          // W: 512 chunks per tensor
        int idx = tid + i * 256;
        int r = idx >> 2, c = idx & 3;
        uint32_t soff = (uint32_t)(r * ROWB + c * 16);
        const __nv_bfloat16* gh = g_whi + (size_t)(n0 + r) * D_IN + k0 + c * 8;
        const __nv_bfloat16* gl = g_wlo + (size_t)(n0 + r) * D_IN + k0 + c * 8;
        CP_ASYNC16(sbase + 2 * XB + soff, gh);
        CP_ASYNC16(sbase + 2 * XB + WB + soff, gl);
    }
}

__global__ void __launch_bounds__(NTHREADS, 1) main_mma_kernel(
    const float* __restrict__ b0v, const float* __restrict__ W2)
{
    extern __shared__ __align__(128) char smem[];
    const uint32_t sb = smem_u32(smem);
    const int tid  = threadIdx.x;
    const int wid  = tid >> 5;
    const int lane = tid & 31;
    const int wm   = wid >> 1;           // 0..3  (64-row slice)
    const int wn   = wid & 1;            // 0..1  (64-col slice)
    const int n0   = blockIdx.x * BN;
    const int b0   = blockIdx.y * BM;

    // stage bias / W2
    if (tid < BN) {
        ((float*)(smem + BIAS_OFF))[tid] = b0v[n0 + tid];
        ((float*)(smem + W2_OFF))[tid]   = W2[n0 + tid];
    }

    float acc[4][8][4];
#pragma unroll
    for (int mt = 0; mt < 4; ++mt)
#pragma unroll
        for (int nt = 0; nt < 8; ++nt)
#pragma unroll
            for (int e = 0; e < 4; ++e) acc[mt][nt][e] = 0.f;

    // per-lane ldmatrix offsets
    const uint32_t aoff = (uint32_t)((lane & 15) * ROWB + (lane >> 4) * 16);
    const uint32_t boff = (uint32_t)((((lane & 7) + ((lane >> 4) << 3)) * ROWB) + ((lane >> 3) & 1) * 16);

    issue_stage(sb, 0, b0, n0, tid);
    CP_COMMIT();

    for (int it = 0; it < KITERS; ++it) {
        __syncthreads();    // all warps done reading the buffer we're about to refill
        if (it + 1 < KITERS) {
            issue_stage(sb + (uint32_t)(((it + 1) & 1) * STAGEB), (it + 1) * BK, b0, n0, tid);
            CP_COMMIT();
            CP_WAIT(1);
        } else {
            CP_WAIT(0);
        }
        __syncthreads();

        const uint32_t st = sb + (uint32_t)((it & 1) * STAGEB);
#pragma unroll
        for (int ks = 0; ks < 2; ++ks) {
            const uint32_t kb = (uint32_t)(ks * 32);
            uint32_t a_hi[4][4], a_lo[4][4], b_hi[4][4], b_lo[4][4];
#pragma unroll
            for (int mt = 0; mt < 4; ++mt) {
                uint32_t ad = st + (uint32_t)((wm * 64 + mt * 16) * ROWB) + kb + aoff;
                ldsm4(a_hi[mt], ad);
                ldsm4(a_lo[mt], ad + XB);
            }
#pragma unroll
            for (int bt = 0; bt < 4; ++bt) {
                uint32_t bd = st + 2 * XB + (uint32_t)((wn * 64 + bt * 16) * ROWB) + kb + boff;
                ldsm4(b_hi[bt], bd);
                ldsm4(b_lo[bt], bd + WB);
            }
#pragma unroll
            for (int mt = 0; mt < 4; ++mt) {
#pragma unroll
                for (int nt = 0; nt < 8; ++nt) {
                    const uint32_t* bh = &b_hi[nt >> 1][(nt & 1) * 2];
                    const uint32_t* bl = &b_lo[nt >> 1][(nt & 1) * 2];
                    mma16816(acc[mt][nt], a_hi[mt], bh);
                    mma16816(acc[mt][nt], a_lo[mt], bh);
                    mma16816(acc[mt][nt], a_hi[mt], bl);
                }
            }
        }
    }

    // ---- epilogue: relu(h + bias) . W2, reduced along the 128 local cols ----
    const float* bias = (const float*)(smem + BIAS_OFF);
    const float* w2s  = (const float*)(smem + W2_OFF);
    float* red        = (float*)(smem + RED_OFF);   // [BM][2]

    __syncthreads();   // everyone done with tile smem (red is separate, but keep ordering clean)

#pragma unroll
    for (int mt = 0; mt < 4; ++mt) {
#pragma unroll
        for (int h = 0; h < 2; ++h) {
            float s = 0.f;
#pragma unroll
            for (int nt = 0; nt < 8; ++nt) {
#pragma unroll
                for (int e = 0; e < 2; ++e) {
                    int col = wn * 64 + nt * 8 + (lane & 3) * 2 + e;
                    float hv = acc[mt][nt][h * 2 + e] + bias[col];
                    s = fmaf(fmaxf(hv, 0.f), w2s[col], s);
                }
            }
            s += __shfl_xor_sync(0xffffffffu, s, 1);
            s += __shfl_xor_sync(0xffffffffu, s, 2);
            if ((lane & 3) == 0) {
                int row = wm * 64 + mt * 16 + (lane >> 2) + h * 8;
                red[row * 2 + wn] = s;
            }
        }
    }
    __syncthreads();

    // combine the two n-warps, write per-(n-tile) partial
    {
        int row = tid;   // 0..255
        float s = red[row * 2] + red[row * 2 + 1];
        g_partial[(size_t)blockIdx.x * BATCH + b0 + row] = s;
    }
}

// ==================================================================
// Kernel D: out[b] = b2 + sum_nt partial[nt][b]
// ==================================================================
__global__ __launch_bounds__(256) void finalize_kernel(
    const float* __restrict__ b2, float* __restrict__ out)
{
    int b = blockIdx.x * 256 + threadIdx.x;
    float s = b2[0];
#pragma unroll
    for (int t = 0; t < NT; ++t)
        s += g_partial[(size_t)t * BATCH + b];
    out[b] = s;
}

// ==================================================================
extern "C" void kernel_launch(void* const* d_in, const int* in_sizes, int n_in,
                              void* d_out, int out_size)
{
    const float* x   = (const float*)d_in[0];
    const float* W0  = (const float*)d_in[1];
    const float* b0v = (const float*)d_in[2];
    const float* A   = (const float*)d_in[3];
    const float* Bm  = (const float*)d_in[4];
    const float* W2  = (const float*)d_in[5];
    const float* b2  = (const float*)d_in[6];
    float* out = (float*)d_out;

    cudaFuncSetAttribute(main_mma_kernel,
                         cudaFuncAttributeMaxDynamicSharedMemorySize, SMEM_TOTAL);

    split_x_kernel<<<(BATCH * D_IN) / (256 * 4), 256>>>(x);
    weff_split_kernel<<<M_HID, 256>>>(W0, A, Bm);

    dim3 grid(NT, MT);
    main_mma_kernel<<<grid, NTHREADS, SMEM_TOTAL>>>(b0v, W2);

    finalize_kernel<<<BATCH / 256, 256>>>(b2, out);
}